// round 1
// baseline (speedup 1.0000x reference)
#include <cuda_runtime.h>
#include <cooperative_groups.h>

namespace cg = cooperative_groups;

#define T_SEQ 4096
#define IN_DIM 512
#define H_DIM  256
#define G_DIM  1024   // 4*H

// ---------------- scratch (no allocation allowed -> device globals) ----------------
__device__ float g_x  [T_SEQ * IN_DIM];   // embedded tokens
__device__ float g_Gf [T_SEQ * G_DIM];    // precomputed input gates, forward (step order)
__device__ float g_Gb [T_SEQ * G_DIM];    // precomputed input gates, backward (step order)
__device__ float g_h0f[T_SEQ * H_DIM];    // layer-0 forward hidden sequence
__device__ float g_h0b[T_SEQ * H_DIM];    // layer-0 backward hidden sequence (step order)

// ---------------- embedding gather ----------------
__global__ void embed_kernel(const int* __restrict__ tokens,
                             const float* __restrict__ emb,
                             float* __restrict__ x)
{
    int t = blockIdx.x;
    int tok = tokens[t];
    const float4* src = (const float4*)(emb + (size_t)tok * IN_DIM);
    float4* dst = (float4*)(x + (size_t)t * IN_DIM);
    dst[threadIdx.x] = src[threadIdx.x];   // 128 threads * float4 = 512 floats
}

// ---------------- C[M,N] = A[M,K] @ W[N,K]^T + b1[N] + b2[N]  (optionally reading A rows reversed) ----------------
__global__ __launch_bounds__(256)
void gemm_nt_bias(const float* __restrict__ A, const float* __restrict__ W,
                  const float* __restrict__ b1, const float* __restrict__ b2,
                  float* __restrict__ C, int M, int N, int K, int revA)
{
    __shared__ float As[64][17];
    __shared__ float Bs[64][17];
    int bm = blockIdx.y * 64, bn = blockIdx.x * 64;
    int tid = threadIdx.x;
    int lk = tid & 15, lr = tid >> 4;     // load coords
    int tx = tid & 15, ty = tid >> 4;     // compute coords

    float acc[4][4];
#pragma unroll
    for (int i = 0; i < 4; i++)
#pragma unroll
        for (int j = 0; j < 4; j++) acc[i][j] = 0.f;

    for (int k0 = 0; k0 < K; k0 += 16) {
#pragma unroll
        for (int r = 0; r < 4; r++) {
            int row = lr + r * 16;
            int am = bm + row;
            int as = revA ? (M - 1 - am) : am;
            As[row][lk] = A[(size_t)as * K + k0 + lk];
            Bs[row][lk] = W[(size_t)(bn + row) * K + k0 + lk];
        }
        __syncthreads();
#pragma unroll
        for (int k = 0; k < 16; k++) {
            float a[4], b[4];
#pragma unroll
            for (int i = 0; i < 4; i++) a[i] = As[ty * 4 + i][k];
#pragma unroll
            for (int j = 0; j < 4; j++) b[j] = Bs[tx * 4 + j][k];
#pragma unroll
            for (int i = 0; i < 4; i++)
#pragma unroll
                for (int j = 0; j < 4; j++) acc[i][j] += a[i] * b[j];
        }
        __syncthreads();
    }

#pragma unroll
    for (int i = 0; i < 4; i++) {
        int m = bm + ty * 4 + i;
#pragma unroll
        for (int j = 0; j < 4; j++) {
            int n = bn + tx * 4 + j;
            C[(size_t)m * N + n] = acc[i][j] + b1[n] + b2[n];
        }
    }
}

// ---------------- LSTM recurrence: one 8-CTA cluster per direction ----------------
__device__ __forceinline__ float sigf(float x) { return 1.f / (1.f + __expf(-x)); }

__global__ __launch_bounds__(256, 1) __cluster_dims__(8, 1, 1)
void lstm_layer_kernel(const float* __restrict__ Gf, const float* __restrict__ Gb,
                       const float* __restrict__ Whh_f, const float* __restrict__ Whh_b,
                       float* __restrict__ outf, float* __restrict__ outb,
                       int out_stride, int rev_out_b,
                       float* __restrict__ cellf, float* __restrict__ cellb,
                       float* __restrict__ hidf,  float* __restrict__ hidb)
{
    cg::cluster_group cluster = cg::this_cluster();
    const int crank = cluster.block_rank();          // 0..7 within direction cluster
    const int dir   = blockIdx.x >> 3;               // 0 = forward, 1 = backward

    const float* G    = dir ? Gb    : Gf;
    const float* Whh  = dir ? Whh_b : Whh_f;
    float* outp       = dir ? outb  : outf;
    float* cell_dst   = dir ? cellb : cellf;
    float* hid_dst    = dir ? hidb  : hidf;
    const int rev_out = dir ? rev_out_b : 0;

    const int tid = threadIdx.x;
    const int rg = tid >> 4;          // rowgroup 0..15 (8 local rows each)
    const int ks = tid & 15;          // k-split 0..15 (16 k-values each)

    __shared__ float hbuf[2][H_DIM];  // double-buffered full h vector
    __shared__ float gbuf[128];       // reduced gate values, local rows

    // ---- load this thread's Whh slice into registers (8 rows x 16 k) ----
    float w[8][16];
#pragma unroll
    for (int r = 0; r < 8; r++) {
        int lrow = rg * 8 + r;                               // local row 0..127
        int grow = (lrow >> 5) * H_DIM + crank * 32 + (lrow & 31); // global gate row
        const float4* wp = (const float4*)(Whh + (size_t)grow * H_DIM + ks * 16);
#pragma unroll
        for (int j = 0; j < 4; j++) {
            float4 v = wp[j];
            w[r][4 * j + 0] = v.x; w[r][4 * j + 1] = v.y;
            w[r][4 * j + 2] = v.z; w[r][4 * j + 3] = v.w;
        }
    }

    hbuf[0][tid] = 0.f;          // 256 threads cover 256 entries
    float cstate = 0.f;          // valid in warp 0 lanes (one hidden unit each)
    cluster.sync();

    for (int t = 0; t < T_SEQ; t++) {
        const int buf = t & 1, nb = buf ^ 1;

        // prefetch precomputed input gates for this step (hidden under FMA phase)
        float gI = 0.f, gF = 0.f, gG = 0.f, gO = 0.f;
        if (tid < 32) {
            const float* Gt = G + (size_t)t * G_DIM + crank * 32 + tid;
            gI = __ldg(Gt);
            gF = __ldg(Gt + 256);
            gG = __ldg(Gt + 512);
            gO = __ldg(Gt + 768);
        }

        // ---- h slice -> registers ----
        float hreg[16];
        const float4* hp = (const float4*)&hbuf[buf][ks * 16];
#pragma unroll
        for (int j = 0; j < 4; j++) {
            float4 v = hp[j];
            hreg[4 * j + 0] = v.x; hreg[4 * j + 1] = v.y;
            hreg[4 * j + 2] = v.z; hreg[4 * j + 3] = v.w;
        }

        // ---- partial dot products: 8 rows x 16 k ----
        float acc[8];
#pragma unroll
        for (int r = 0; r < 8; r++) {
            float s = 0.f;
#pragma unroll
            for (int k = 0; k < 16; k++) s += w[r][k] * hreg[k];
            acc[r] = s;
        }

        // ---- reduce across the 16 k-split lanes (xor <= 8 stays in 16-lane halves) ----
#pragma unroll
        for (int s = 8; s >= 1; s >>= 1)
#pragma unroll
            for (int r = 0; r < 8; r++)
                acc[r] += __shfl_xor_sync(0xffffffffu, acc[r], s);

        if (ks < 8) {
#pragma unroll
            for (int r = 0; r < 8; r++)
                if (ks == r) gbuf[rg * 8 + r] = acc[r];
        }
        __syncthreads();

        // ---- elementwise LSTM cell (warp 0: one hidden unit per lane) ----
        if (tid < 32) {
            const int u = tid;
            float iv = gbuf[u]      + gI;
            float fv = gbuf[32 + u] + gF;
            float gv = gbuf[64 + u] + gG;
            float ov = gbuf[96 + u] + gO;
            cstate = sigf(fv) * cstate + sigf(iv) * tanhf(gv);
            float h = sigf(ov) * tanhf(cstate);

            const int gu = crank * 32 + u;   // global hidden index
            // broadcast new h to every CTA in the cluster (incl. self)
#pragma unroll
            for (int rk = 0; rk < 8; rk++) {
                float* ph = (float*)cluster.map_shared_rank((void*)&hbuf[nb][gu], rk);
                *ph = h;
            }
            int orow = rev_out ? (T_SEQ - 1 - t) : t;
            outp[(size_t)orow * out_stride + gu] = h;
            if (t == T_SEQ - 1) {
                cell_dst[gu] = cstate;
                hid_dst[gu]  = h;
            }
        }
        cluster.sync();
    }
}

// ---------------- launch ----------------
extern "C" void kernel_launch(void* const* d_in, const int* in_sizes, int n_in,
                              void* d_out, int out_size)
{
    const int*   tokens  = (const int*)  d_in[0];
    const float* emb     = (const float*)d_in[1];
    const float* f_Wih0  = (const float*)d_in[2];
    const float* f_Whh0  = (const float*)d_in[3];
    const float* f_bih0  = (const float*)d_in[4];
    const float* f_bhh0  = (const float*)d_in[5];
    const float* f_Wih1  = (const float*)d_in[6];
    const float* f_Whh1  = (const float*)d_in[7];
    const float* f_bih1  = (const float*)d_in[8];
    const float* f_bhh1  = (const float*)d_in[9];
    const float* b_Wih0  = (const float*)d_in[10];
    const float* b_Whh0  = (const float*)d_in[11];
    const float* b_bih0  = (const float*)d_in[12];
    const float* b_bhh0  = (const float*)d_in[13];
    const float* b_Wih1  = (const float*)d_in[14];
    const float* b_Whh1  = (const float*)d_in[15];
    const float* b_bih1  = (const float*)d_in[16];
    const float* b_bhh1  = (const float*)d_in[17];
    float* out = (float*)d_out;

    float *x, *Gf, *Gb, *h0f, *h0b;
    cudaGetSymbolAddress((void**)&x,   g_x);
    cudaGetSymbolAddress((void**)&Gf,  g_Gf);
    cudaGetSymbolAddress((void**)&Gb,  g_Gb);
    cudaGetSymbolAddress((void**)&h0f, g_h0f);
    cudaGetSymbolAddress((void**)&h0b, g_h0b);

    // output layout: [cell (2,2,256)] [hidden (2,2,256)] [outputs (4096,512)]
    float* cell = out;            // 1024
    float* hid  = out + 1024;     // 1024
    float* outs = out + 2048;     // 4096*512

    // 1) embedding
    embed_kernel<<<T_SEQ, IN_DIM / 4>>>(tokens, emb, x);

    dim3 gemm_grid(G_DIM / 64, T_SEQ / 64);

    // 2) layer-0 input projections (backward reads x reversed -> step-order G)
    gemm_nt_bias<<<gemm_grid, 256>>>(x, f_Wih0, f_bih0, f_bhh0, Gf, T_SEQ, G_DIM, IN_DIM, 0);
    gemm_nt_bias<<<gemm_grid, 256>>>(x, b_Wih0, b_bih0, b_bhh0, Gb, T_SEQ, G_DIM, IN_DIM, 1);

    // 3) layer-0 recurrence (both directions in one launch: 2 clusters x 8 CTAs)
    lstm_layer_kernel<<<16, 256>>>(Gf, Gb, f_Whh0, b_Whh0,
                                   h0f, h0b, H_DIM, /*rev_out_b=*/0,
                                   cell + 0,   cell + 256,
                                   hid  + 0,   hid  + 256);

    // 4) layer-1 input projections (inputs already in step order)
    gemm_nt_bias<<<gemm_grid, 256>>>(h0f, f_Wih1, f_bih1, f_bhh1, Gf, T_SEQ, G_DIM, H_DIM, 0);
    gemm_nt_bias<<<gemm_grid, 256>>>(h0b, b_Wih1, b_bih1, b_bhh1, Gb, T_SEQ, G_DIM, H_DIM, 0);

    // 5) layer-1 recurrence: writes directly into outputs (backward rows reversed, cols 256..511)
    lstm_layer_kernel<<<16, 256>>>(Gf, Gb, f_Whh1, b_Whh1,
                                   outs, outs + 256, 2 * H_DIM, /*rev_out_b=*/1,
                                   cell + 512, cell + 768,
                                   hid  + 512, hid  + 768);
}

// round 2
// speedup vs baseline: 1.0508x; 1.0508x over previous
#include <cuda_runtime.h>
#include <cooperative_groups.h>

namespace cg = cooperative_groups;

#define T_SEQ 4096
#define IN_DIM 512
#define H_DIM  256
#define G_DIM  1024   // 4*H

// ---------------- scratch (no allocation allowed -> device globals) ----------------
__device__ float g_x  [T_SEQ * IN_DIM];   // embedded tokens
__device__ float g_Gf [T_SEQ * G_DIM];    // precomputed input gates, forward (step order)
__device__ float g_Gb [T_SEQ * G_DIM];    // precomputed input gates, backward (step order)
__device__ float g_h0f[T_SEQ * H_DIM];    // layer-0 forward hidden sequence
__device__ float g_h0b[T_SEQ * H_DIM];    // layer-0 backward hidden sequence (step order)

// ---------------- small PTX helpers ----------------
__device__ __forceinline__ unsigned long long ffma2(unsigned long long a,
                                                    unsigned long long b,
                                                    unsigned long long c)
{
    unsigned long long d;
    asm("fma.rn.f32x2 %0, %1, %2, %3;" : "=l"(d) : "l"(a), "l"(b), "l"(c));
    return d;
}
__device__ __forceinline__ unsigned long long packf2(float lo, float hi)
{
    unsigned long long d;
    asm("mov.b64 %0, {%1, %2};" : "=l"(d) : "f"(lo), "f"(hi));
    return d;
}
__device__ __forceinline__ float lof2(unsigned long long v)
{
    float f; asm("{ .reg .b32 hi; mov.b64 {%0, hi}, %1; }" : "=f"(f) : "l"(v)); return f;
}
__device__ __forceinline__ float hif2(unsigned long long v)
{
    float f; asm("{ .reg .b32 lo; mov.b64 {lo, %0}, %1; }" : "=f"(f) : "l"(v)); return f;
}
__device__ __forceinline__ unsigned smem_u32(const void* p)
{
    return (unsigned)__cvta_generic_to_shared(p);
}
__device__ __forceinline__ unsigned mapa_u32(unsigned addr, unsigned rank)
{
    unsigned r;
    asm("mapa.shared::cluster.u32 %0, %1, %2;" : "=r"(r) : "r"(addr), "r"(rank));
    return r;
}
__device__ __forceinline__ void mbar_init(unsigned bar, unsigned cnt)
{
    asm volatile("mbarrier.init.shared::cta.b64 [%0], %1;" :: "r"(bar), "r"(cnt) : "memory");
}
__device__ __forceinline__ void mbar_expect_tx(unsigned bar, unsigned bytes)
{
    asm volatile("mbarrier.arrive.expect_tx.shared::cta.b64 _, [%0], %1;"
                 :: "r"(bar), "r"(bytes) : "memory");
}
__device__ __forceinline__ void mbar_wait(unsigned bar, unsigned parity)
{
    asm volatile(
        "{\n\t"
        ".reg .pred P1;\n\t"
        "LW_%=:\n\t"
        "mbarrier.try_wait.parity.acquire.cta.shared::cta.b64 P1, [%0], %1, 0x989680;\n\t"
        "@P1 bra LD_%=;\n\t"
        "bra LW_%=;\n\t"
        "LD_%=:\n\t"
        "}"
        :: "r"(bar), "r"(parity) : "memory");
}
__device__ __forceinline__ void bulk_s2s(unsigned dst, unsigned src, unsigned bytes, unsigned rbar)
{
    asm volatile(
        "cp.async.bulk.shared::cluster.shared::cta.mbarrier::complete_tx::bytes [%0], [%1], %2, [%3];"
        :: "r"(dst), "r"(src), "r"(bytes), "r"(rbar) : "memory");
}

__device__ __forceinline__ float sigf(float x)
{
    return __fdividef(1.f, 1.f + __expf(-x));
}
__device__ __forceinline__ float tanh_fast(float x)
{
    return __fdividef(2.f, 1.f + __expf(-2.f * x)) - 1.f;
}

// ---------------- embedding gather ----------------
__global__ void embed_kernel(const int* __restrict__ tokens,
                             const float* __restrict__ emb,
                             float* __restrict__ x)
{
    int t = blockIdx.x;
    int tok = tokens[t];
    const float4* src = (const float4*)(emb + (size_t)tok * IN_DIM);
    float4* dst = (float4*)(x + (size_t)t * IN_DIM);
    dst[threadIdx.x] = src[threadIdx.x];
}

// ---------------- C[M,N] = A[M,K] @ W[N,K]^T + b1 + b2 (optional reversed A rows) ----------------
__global__ __launch_bounds__(256)
void gemm_nt_bias(const float* __restrict__ A, const float* __restrict__ W,
                  const float* __restrict__ b1, const float* __restrict__ b2,
                  float* __restrict__ C, int M, int N, int K, int revA)
{
    __shared__ float As[64][17];
    __shared__ float Bs[64][17];
    int bm = blockIdx.y * 64, bn = blockIdx.x * 64;
    int tid = threadIdx.x;
    int lk = tid & 15, lr = tid >> 4;
    int tx = tid & 15, ty = tid >> 4;

    float acc[4][4];
#pragma unroll
    for (int i = 0; i < 4; i++)
#pragma unroll
        for (int j = 0; j < 4; j++) acc[i][j] = 0.f;

    for (int k0 = 0; k0 < K; k0 += 16) {
#pragma unroll
        for (int r = 0; r < 4; r++) {
            int row = lr + r * 16;
            int am = bm + row;
            int as = revA ? (M - 1 - am) : am;
            As[row][lk] = A[(size_t)as * K + k0 + lk];
            Bs[row][lk] = W[(size_t)(bn + row) * K + k0 + lk];
        }
        __syncthreads();
#pragma unroll
        for (int k = 0; k < 16; k++) {
            float a[4], b[4];
#pragma unroll
            for (int i = 0; i < 4; i++) a[i] = As[ty * 4 + i][k];
#pragma unroll
            for (int j = 0; j < 4; j++) b[j] = Bs[tx * 4 + j][k];
#pragma unroll
            for (int i = 0; i < 4; i++)
#pragma unroll
                for (int j = 0; j < 4; j++) acc[i][j] += a[i] * b[j];
        }
        __syncthreads();
    }

#pragma unroll
    for (int i = 0; i < 4; i++) {
        int m = bm + ty * 4 + i;
#pragma unroll
        for (int j = 0; j < 4; j++) {
            int n = bn + tx * 4 + j;
            C[(size_t)m * N + n] = acc[i][j] + b1[n] + b2[n];
        }
    }
}

// ---------------- LSTM recurrence: 8-CTA cluster per direction, mbarrier h exchange ----------------
__global__ __launch_bounds__(256, 1) __cluster_dims__(8, 1, 1)
void lstm_layer_kernel(const float* __restrict__ Gf, const float* __restrict__ Gb,
                       const float* __restrict__ Whh_f, const float* __restrict__ Whh_b,
                       float* __restrict__ outf, float* __restrict__ outb,
                       int out_stride, int rev_out_b,
                       float* __restrict__ cellf, float* __restrict__ cellb,
                       float* __restrict__ hidf,  float* __restrict__ hidb)
{
    cg::cluster_group cluster = cg::this_cluster();
    const int crank = cluster.block_rank();
    const int dir   = blockIdx.x >> 3;

    const float* G    = dir ? Gb    : Gf;
    const float* Whh  = dir ? Whh_b : Whh_f;
    float* outp       = dir ? outb  : outf;
    float* cell_dst   = dir ? cellb : cellf;
    float* hid_dst    = dir ? hidb  : hidf;
    const int rev_out = dir ? rev_out_b : 0;

    const int tid = threadIdx.x;
    const int rg = tid >> 4;          // rowgroup 0..15 (8 local rows each)
    const int ks = tid & 15;          // k-split 0..15 (16 k-values each)

    __shared__ __align__(16) float hbuf[2][H_DIM];    // ping-pong h input buffers
    __shared__ __align__(16) float hstage[2][32];     // this CTA's 32 new h values
    __shared__ float gbuf[128];
    __shared__ __align__(8) unsigned long long barmem[2];

    const unsigned hbuf_a   = smem_u32(&hbuf[0][0]);
    const unsigned hstage_a = smem_u32(&hstage[0][0]);
    const unsigned bar_a    = smem_u32(&barmem[0]);

    // ---- Whh slice -> registers as f32x2 pairs: 8 rows x 8 k-pairs ----
    unsigned long long w2[8][8];
#pragma unroll
    for (int r = 0; r < 8; r++) {
        int lrow = rg * 8 + r;
        int grow = (lrow >> 5) * H_DIM + crank * 32 + (lrow & 31);
        const float4* wp = (const float4*)(Whh + (size_t)grow * H_DIM + ks * 16);
#pragma unroll
        for (int j = 0; j < 4; j++) {
            float4 v = wp[j];
            w2[r][2 * j + 0] = packf2(v.x, v.y);
            w2[r][2 * j + 1] = packf2(v.z, v.w);
        }
    }

    hbuf[0][tid] = 0.f;
    if (tid == 0) {
        mbar_init(bar_a + 0, 1);
        mbar_init(bar_a + 8, 1);
        mbar_expect_tx(bar_a + 0, 1024);   // serves step 2
        mbar_expect_tx(bar_a + 8, 1024);   // serves step 1
    }

    // remote base addresses for all 8 cluster ranks
    unsigned rhb[8], rbb[8];
#pragma unroll
    for (int rk = 0; rk < 8; rk++) {
        rhb[rk] = mapa_u32(hbuf_a, rk);
        rbb[rk] = mapa_u32(bar_a, rk);
    }

    float cstate = 0.f;
    cluster.sync();   // barriers armed + hbuf[0] zeroed everywhere

    for (int t = 0; t < T_SEQ; t++) {
        const int buf = t & 1, nb = buf ^ 1;

        if (t > 0) {
            mbar_wait(bar_a + 8 * buf, ((t - 1) >> 1) & 1);
            if (tid == 0) mbar_expect_tx(bar_a + 8 * buf, 1024);  // re-arm for step t+2
        }

        // prefetch precomputed input gates (hidden under FMA phase)
        float gI = 0.f, gF = 0.f, gG = 0.f, gO = 0.f;
        if (tid < 32) {
            const float* Gt = G + (size_t)t * G_DIM + crank * 32 + tid;
            gI = __ldg(Gt);
            gF = __ldg(Gt + 256);
            gG = __ldg(Gt + 512);
            gO = __ldg(Gt + 768);
        }

        // ---- h slice -> f32x2 registers ----
        unsigned long long h2[8];
        {
            const ulonglong2* hp = (const ulonglong2*)&hbuf[buf][ks * 16];
#pragma unroll
            for (int j = 0; j < 4; j++) {
                ulonglong2 v = hp[j];
                h2[2 * j + 0] = v.x;
                h2[2 * j + 1] = v.y;
            }
        }

        // ---- packed partial dot products: 8 rows x 8 pairs ----
        unsigned long long acc2[8];
#pragma unroll
        for (int r = 0; r < 8; r++) acc2[r] = 0ull;
#pragma unroll
        for (int j = 0; j < 8; j++)
#pragma unroll
            for (int r = 0; r < 8; r++)
                acc2[r] = ffma2(w2[r][j], h2[j], acc2[r]);

        float acc[8];
#pragma unroll
        for (int r = 0; r < 8; r++) acc[r] = lof2(acc2[r]) + hif2(acc2[r]);

        // ---- reduce across 16 k-split lanes ----
#pragma unroll
        for (int s = 8; s >= 1; s >>= 1)
#pragma unroll
            for (int r = 0; r < 8; r++)
                acc[r] += __shfl_xor_sync(0xffffffffu, acc[r], s);

        if (ks < 8) {
#pragma unroll
            for (int r = 0; r < 8; r++)
                if (ks == r) gbuf[rg * 8 + r] = acc[r];
        }
        __syncthreads();

        // ---- elementwise LSTM cell + broadcast (warp 0) ----
        if (tid < 32) {
            const int u = tid;
            float iv = gbuf[u]      + gI;
            float fv = gbuf[32 + u] + gF;
            float gv = gbuf[64 + u] + gG;
            float ov = gbuf[96 + u] + gO;
            cstate = sigf(fv) * cstate + sigf(iv) * tanh_fast(gv);
            float h = sigf(ov) * tanh_fast(cstate);

            const int gu = crank * 32 + u;
            hstage[nb][u] = h;

            int orow = rev_out ? (T_SEQ - 1 - t) : t;
            outp[(size_t)orow * out_stride + gu] = h;
            if (t == T_SEQ - 1) {
                cell_dst[gu] = cstate;
                hid_dst[gu]  = h;
            }
            __syncwarp();

            if (t < T_SEQ - 1 && u == 0) {
                asm volatile("fence.proxy.async.shared::cta;" ::: "memory");
                unsigned src  = hstage_a + nb * 128;
                unsigned hoff = (unsigned)(nb * H_DIM * 4 + crank * 128);
                unsigned boff = (unsigned)(8 * nb);
#pragma unroll
                for (int rk = 0; rk < 8; rk++)
                    bulk_s2s(rhb[rk] + hoff, src, 128, rbb[rk] + boff);
            }
        }
    }
    cluster.sync();
}

// ---------------- launch ----------------
extern "C" void kernel_launch(void* const* d_in, const int* in_sizes, int n_in,
                              void* d_out, int out_size)
{
    const int*   tokens  = (const int*)  d_in[0];
    const float* emb     = (const float*)d_in[1];
    const float* f_Wih0  = (const float*)d_in[2];
    const float* f_Whh0  = (const float*)d_in[3];
    const float* f_bih0  = (const float*)d_in[4];
    const float* f_bhh0  = (const float*)d_in[5];
    const float* f_Wih1  = (const float*)d_in[6];
    const float* f_Whh1  = (const float*)d_in[7];
    const float* f_bih1  = (const float*)d_in[8];
    const float* f_bhh1  = (const float*)d_in[9];
    const float* b_Wih0  = (const float*)d_in[10];
    const float* b_Whh0  = (const float*)d_in[11];
    const float* b_bih0  = (const float*)d_in[12];
    const float* b_bhh0  = (const float*)d_in[13];
    const float* b_Wih1  = (const float*)d_in[14];
    const float* b_Whh1  = (const float*)d_in[15];
    const float* b_bih1  = (const float*)d_in[16];
    const float* b_bhh1  = (const float*)d_in[17];
    float* out = (float*)d_out;

    float *x, *Gf, *Gb, *h0f, *h0b;
    cudaGetSymbolAddress((void**)&x,   g_x);
    cudaGetSymbolAddress((void**)&Gf,  g_Gf);
    cudaGetSymbolAddress((void**)&Gb,  g_Gb);
    cudaGetSymbolAddress((void**)&h0f, g_h0f);
    cudaGetSymbolAddress((void**)&h0b, g_h0b);

    float* cell = out;            // (2,2,256)
    float* hid  = out + 1024;     // (2,2,256)
    float* outs = out + 2048;     // (4096,512)

    embed_kernel<<<T_SEQ, IN_DIM / 4>>>(tokens, emb, x);

    dim3 gemm_grid(G_DIM / 64, T_SEQ / 64);

    gemm_nt_bias<<<gemm_grid, 256>>>(x, f_Wih0, f_bih0, f_bhh0, Gf, T_SEQ, G_DIM, IN_DIM, 0);
    gemm_nt_bias<<<gemm_grid, 256>>>(x, b_Wih0, b_bih0, b_bhh0, Gb, T_SEQ, G_DIM, IN_DIM, 1);

    lstm_layer_kernel<<<16, 256>>>(Gf, Gb, f_Whh0, b_Whh0,
                                   h0f, h0b, H_DIM, 0,
                                   cell + 0,   cell + 256,
                                   hid  + 0,   hid  + 256);

    gemm_nt_bias<<<gemm_grid, 256>>>(h0f, f_Wih1, f_bih1, f_bhh1, Gf, T_SEQ, G_DIM, H_DIM, 0);
    gemm_nt_bias<<<gemm_grid, 256>>>(h0b, b_Wih1, b_bih1, b_bhh1, Gb, T_SEQ, G_DIM, H_DIM, 0);

    lstm_layer_kernel<<<16, 256>>>(Gf, Gb, f_Whh1, b_Whh1,
                                   outs, outs + 256, 2 * H_DIM, 1,
                                   cell + 512, cell + 768,
                                   hid  + 512, hid  + 768);
}

// round 3
// speedup vs baseline: 1.4158x; 1.3474x over previous
#include <cuda_runtime.h>
#include <cooperative_groups.h>

namespace cg = cooperative_groups;

#define T_SEQ 4096
#define IN_DIM 512
#define H_DIM  256
#define G_DIM  1024   // 4*H

// ---------------- scratch (no allocation allowed -> device globals) ----------------
__device__ float g_x  [T_SEQ * IN_DIM];
__device__ float g_Gf [T_SEQ * G_DIM];
__device__ float g_Gb [T_SEQ * G_DIM];
__device__ float g_h0f[T_SEQ * H_DIM];
__device__ float g_h0b[T_SEQ * H_DIM];

// ---------------- PTX helpers ----------------
__device__ __forceinline__ unsigned long long ffma2(unsigned long long a,
                                                    unsigned long long b,
                                                    unsigned long long c)
{
    unsigned long long d;
    asm("fma.rn.f32x2 %0, %1, %2, %3;" : "=l"(d) : "l"(a), "l"(b), "l"(c));
    return d;
}
__device__ __forceinline__ unsigned long long packf2(float lo, float hi)
{
    unsigned long long d;
    asm("mov.b64 %0, {%1, %2};" : "=l"(d) : "f"(lo), "f"(hi));
    return d;
}
__device__ __forceinline__ float lof2(unsigned long long v)
{
    float f; asm("{ .reg .b32 hi; mov.b64 {%0, hi}, %1; }" : "=f"(f) : "l"(v)); return f;
}
__device__ __forceinline__ float hif2(unsigned long long v)
{
    float f; asm("{ .reg .b32 lo; mov.b64 {lo, %0}, %1; }" : "=f"(f) : "l"(v)); return f;
}
__device__ __forceinline__ unsigned smem_u32(const void* p)
{
    return (unsigned)__cvta_generic_to_shared(p);
}
__device__ __forceinline__ unsigned mapa_u32(unsigned addr, unsigned rank)
{
    unsigned r;
    asm("mapa.shared::cluster.u32 %0, %1, %2;" : "=r"(r) : "r"(addr), "r"(rank));
    return r;
}
__device__ __forceinline__ void mbar_init(unsigned bar, unsigned cnt)
{
    asm volatile("mbarrier.init.shared::cta.b64 [%0], %1;" :: "r"(bar), "r"(cnt) : "memory");
}
__device__ __forceinline__ void mbar_expect_tx(unsigned bar, unsigned bytes)
{
    asm volatile("mbarrier.arrive.expect_tx.shared::cta.b64 _, [%0], %1;"
                 :: "r"(bar), "r"(bytes) : "memory");
}
__device__ __forceinline__ void mbar_wait(unsigned bar, unsigned parity)
{
    asm volatile(
        "{\n\t"
        ".reg .pred P1;\n\t"
        "LW_%=:\n\t"
        "mbarrier.try_wait.parity.acquire.cta.shared::cta.b64 P1, [%0], %1, 0x989680;\n\t"
        "@P1 bra LD_%=;\n\t"
        "bra LW_%=;\n\t"
        "LD_%=:\n\t"
        "}"
        :: "r"(bar), "r"(parity) : "memory");
}
// scalar async store to remote (cluster) smem with tx-credit on remote barrier
__device__ __forceinline__ void st_async_f32(unsigned dst, float val, unsigned rbar)
{
    asm volatile(
        "st.async.shared::cluster.mbarrier::complete_tx::bytes.b32 [%0], %1, [%2];"
        :: "r"(dst), "r"(__float_as_uint(val)), "r"(rbar) : "memory");
}

__device__ __forceinline__ float sigf(float x)
{
    return __fdividef(1.f, 1.f + __expf(-x));
}
__device__ __forceinline__ float tanh_fast(float x)
{
    return __fdividef(2.f, 1.f + __expf(-2.f * x)) - 1.f;
}

// ---------------- embedding gather ----------------
__global__ void embed_kernel(const int* __restrict__ tokens,
                             const float* __restrict__ emb,
                             float* __restrict__ x)
{
    int t = blockIdx.x;
    int tok = tokens[t];
    const float4* src = (const float4*)(emb + (size_t)tok * IN_DIM);
    float4* dst = (float4*)(x + (size_t)t * IN_DIM);
    dst[threadIdx.x] = src[threadIdx.x];
}

// ---------------- C[M,N] = A[M,K] @ W[N,K]^T + b1 + b2 (optional reversed A rows) ----------------
__global__ __launch_bounds__(256)
void gemm_nt_bias(const float* __restrict__ A, const float* __restrict__ W,
                  const float* __restrict__ b1, const float* __restrict__ b2,
                  float* __restrict__ C, int M, int N, int K, int revA)
{
    __shared__ float As[64][17];
    __shared__ float Bs[64][17];
    int bm = blockIdx.y * 64, bn = blockIdx.x * 64;
    int tid = threadIdx.x;
    int lk = tid & 15, lr = tid >> 4;
    int tx = tid & 15, ty = tid >> 4;

    float acc[4][4];
#pragma unroll
    for (int i = 0; i < 4; i++)
#pragma unroll
        for (int j = 0; j < 4; j++) acc[i][j] = 0.f;

    for (int k0 = 0; k0 < K; k0 += 16) {
#pragma unroll
        for (int r = 0; r < 4; r++) {
            int row = lr + r * 16;
            int am = bm + row;
            int as = revA ? (M - 1 - am) : am;
            As[row][lk] = A[(size_t)as * K + k0 + lk];
            Bs[row][lk] = W[(size_t)(bn + row) * K + k0 + lk];
        }
        __syncthreads();
#pragma unroll
        for (int k = 0; k < 16; k++) {
            float a[4], b[4];
#pragma unroll
            for (int i = 0; i < 4; i++) a[i] = As[ty * 4 + i][k];
#pragma unroll
            for (int j = 0; j < 4; j++) b[j] = Bs[tx * 4 + j][k];
#pragma unroll
            for (int i = 0; i < 4; i++)
#pragma unroll
                for (int j = 0; j < 4; j++) acc[i][j] += a[i] * b[j];
        }
        __syncthreads();
    }

#pragma unroll
    for (int i = 0; i < 4; i++) {
        int m = bm + ty * 4 + i;
#pragma unroll
        for (int j = 0; j < 4; j++) {
            int n = bn + tx * 4 + j;
            C[(size_t)m * N + n] = acc[i][j] + b1[n] + b2[n];
        }
    }
}

// ---------------- LSTM recurrence: 8-CTA cluster/direction, warp-autonomous units ----------------
// CTA owns 32 hidden units; warp w owns units [w*4, w*4+4).
// Lane l: r = l>>1 in 0..15 -> (unit_in_warp = r>>2, gate = r&3); kh = l&1 -> k-half.
__global__ __launch_bounds__(256, 1) __cluster_dims__(8, 1, 1)
void lstm_layer_kernel(const float* __restrict__ Gf, const float* __restrict__ Gb,
                       const float* __restrict__ Whh_f, const float* __restrict__ Whh_b,
                       float* __restrict__ outf, float* __restrict__ outb,
                       int out_stride, int rev_out_b,
                       float* __restrict__ cellf, float* __restrict__ cellb,
                       float* __restrict__ hidf,  float* __restrict__ hidb)
{
    cg::cluster_group cluster = cg::this_cluster();
    const int crank = cluster.block_rank();
    const int dir   = blockIdx.x >> 3;

    const float* G    = dir ? Gb    : Gf;
    const float* Whh  = dir ? Whh_b : Whh_f;
    float* outp       = dir ? outb  : outf;
    float* cell_dst   = dir ? cellb : cellf;
    float* hid_dst    = dir ? hidb  : hidf;
    const int rev_out = dir ? rev_out_b : 0;

    const int tid = threadIdx.x;
    const int w   = tid >> 5;         // warp 0..7
    const int l   = tid & 31;         // lane
    const int r   = l >> 1;           // 0..15: unit_in_warp*4 + gate
    const int kh  = l & 1;            // k-half: [kh*128, kh*128+128)
    const int uiw  = r >> 2;          // unit in warp 0..3
    const int gate = r & 3;           // 0=i 1=f 2=g 3=o
    const int gu_mine = crank * 32 + w * 4 + uiw;   // this lane's dot-product unit
    const int gu_ew   = crank * 32 + w * 4 + l;     // elementwise unit (lanes 0..3)

    __shared__ __align__(16) float hbuf[2][H_DIM];
    __shared__ __align__(8) unsigned long long barmem[2];

    const unsigned hbuf_a = smem_u32(&hbuf[0][0]);
    const unsigned bar_a  = smem_u32(&barmem[0]);

    // ---- Whh slice -> registers: 128 floats as 64 f32x2 ----
    unsigned long long w2[64];
    {
        const int grow = gate * H_DIM + gu_mine;
        const float4* wp = (const float4*)(Whh + (size_t)grow * H_DIM + kh * 128);
#pragma unroll
        for (int j = 0; j < 32; j++) {
            float4 v = wp[j];
            w2[2 * j + 0] = packf2(v.x, v.y);
            w2[2 * j + 1] = packf2(v.z, v.w);
        }
    }

    hbuf[0][tid] = 0.f;
    if (tid == 0) {
        mbar_init(bar_a + 0, 1);
        mbar_init(bar_a + 8, 1);
        mbar_expect_tx(bar_a + 0, 1024);
        mbar_expect_tx(bar_a + 8, 1024);
    }

    unsigned rhb[8], rbb[8];
#pragma unroll
    for (int rk = 0; rk < 8; rk++) {
        rhb[rk] = mapa_u32(hbuf_a, rk);
        rbb[rk] = mapa_u32(bar_a, rk);
    }

    float cstate = 0.f;   // valid in lanes 0..3 of each warp

    // preload G for step 0 (lanes 0..3)
    float gI = 0.f, gF = 0.f, gG = 0.f, gO = 0.f;
    if (l < 4) {
        const float* Gt = G + gu_ew;
        gI = __ldg(Gt);
        gF = __ldg(Gt + 256);
        gG = __ldg(Gt + 512);
        gO = __ldg(Gt + 768);
    }

    cluster.sync();

    for (int t = 0; t < T_SEQ; t++) {
        const int buf = t & 1, nb = buf ^ 1;

        if (t > 0) {
            mbar_wait(bar_a + 8 * buf, ((t - 1) >> 1) & 1);
            if (tid == 0) mbar_expect_tx(bar_a + 8 * buf, 1024);  // re-arm for step t+2
        }

        // ---- recurrent dot: 128 MACs via 64 FFMA2, 4 accumulators, chunked h LDS ----
        unsigned long long a0 = 0ull, a1 = 0ull, a2 = 0ull, a3 = 0ull;
        const ulonglong2* hp = (const ulonglong2*)&hbuf[buf][kh * 128];
#pragma unroll
        for (int c = 0; c < 4; c++) {
            ulonglong2 hv[8];
#pragma unroll
            for (int q = 0; q < 8; q++) hv[q] = hp[c * 8 + q];
#pragma unroll
            for (int q = 0; q < 4; q++) {
                a0 = ffma2(w2[c * 16 + 4 * q + 0], hv[2 * q].x,     a0);
                a1 = ffma2(w2[c * 16 + 4 * q + 1], hv[2 * q].y,     a1);
                a2 = ffma2(w2[c * 16 + 4 * q + 2], hv[2 * q + 1].x, a2);
                a3 = ffma2(w2[c * 16 + 4 * q + 3], hv[2 * q + 1].y, a3);
            }
        }
        float v = (lof2(a0) + hif2(a0)) + (lof2(a1) + hif2(a1))
                + (lof2(a2) + hif2(a2)) + (lof2(a3) + hif2(a3));
        v += __shfl_xor_sync(0xffffffffu, v, 1);     // combine k-halves (pair lanes)

        // gather this lane's unit gates (valid for lanes 0..3)
        float rI = __shfl_sync(0xffffffffu, v, (8 * l + 0) & 31);
        float rF = __shfl_sync(0xffffffffu, v, (8 * l + 2) & 31);
        float rG = __shfl_sync(0xffffffffu, v, (8 * l + 4) & 31);
        float rO = __shfl_sync(0xffffffffu, v, (8 * l + 6) & 31);

        if (l < 4) {
            float iv = rI + gI, fv = rF + gF, gv = rG + gG, ov = rO + gO;
            cstate = sigf(fv) * cstate + sigf(iv) * tanh_fast(gv);
            float h = sigf(ov) * tanh_fast(cstate);

            int orow = rev_out ? (T_SEQ - 1 - t) : t;
            outp[(size_t)orow * out_stride + gu_ew] = h;

            if (t < T_SEQ - 1) {
                const unsigned hoff = (unsigned)(nb * (H_DIM * 4) + gu_ew * 4);
                const unsigned boff = (unsigned)(8 * nb);
#pragma unroll
                for (int rk = 0; rk < 8; rk++)
                    st_async_f32(rhb[rk] + hoff, h, rbb[rk] + boff);
            } else {
                cell_dst[gu_ew] = cstate;
                hid_dst[gu_ew]  = h;
            }
        }

        // prefetch G for step t+1 (hidden under next step's FMA phase)
        if (l < 4 && t + 1 < T_SEQ) {
            const float* Gt = G + (size_t)(t + 1) * G_DIM + gu_ew;
            gI = __ldg(Gt);
            gF = __ldg(Gt + 256);
            gG = __ldg(Gt + 512);
            gO = __ldg(Gt + 768);
        }
    }
    cluster.sync();
}

// ---------------- launch ----------------
extern "C" void kernel_launch(void* const* d_in, const int* in_sizes, int n_in,
                              void* d_out, int out_size)
{
    const int*   tokens  = (const int*)  d_in[0];
    const float* emb     = (const float*)d_in[1];
    const float* f_Wih0  = (const float*)d_in[2];
    const float* f_Whh0  = (const float*)d_in[3];
    const float* f_bih0  = (const float*)d_in[4];
    const float* f_bhh0  = (const float*)d_in[5];
    const float* f_Wih1  = (const float*)d_in[6];
    const float* f_Whh1  = (const float*)d_in[7];
    const float* f_bih1  = (const float*)d_in[8];
    const float* f_bhh1  = (const float*)d_in[9];
    const float* b_Wih0  = (const float*)d_in[10];
    const float* b_Whh0  = (const float*)d_in[11];
    const float* b_bih0  = (const float*)d_in[12];
    const float* b_bhh0  = (const float*)d_in[13];
    const float* b_Wih1  = (const float*)d_in[14];
    const float* b_Whh1  = (const float*)d_in[15];
    const float* b_bih1  = (const float*)d_in[16];
    const float* b_bhh1  = (const float*)d_in[17];
    float* out = (float*)d_out;

    float *x, *Gf, *Gb, *h0f, *h0b;
    cudaGetSymbolAddress((void**)&x,   g_x);
    cudaGetSymbolAddress((void**)&Gf,  g_Gf);
    cudaGetSymbolAddress((void**)&Gb,  g_Gb);
    cudaGetSymbolAddress((void**)&h0f, g_h0f);
    cudaGetSymbolAddress((void**)&h0b, g_h0b);

    float* cell = out;            // (2,2,256)
    float* hid  = out + 1024;     // (2,2,256)
    float* outs = out + 2048;     // (4096,512)

    embed_kernel<<<T_SEQ, IN_DIM / 4>>>(tokens, emb, x);

    dim3 gemm_grid(G_DIM / 64, T_SEQ / 64);

    gemm_nt_bias<<<gemm_grid, 256>>>(x, f_Wih0, f_bih0, f_bhh0, Gf, T_SEQ, G_DIM, IN_DIM, 0);
    gemm_nt_bias<<<gemm_grid, 256>>>(x, b_Wih0, b_bih0, b_bhh0, Gb, T_SEQ, G_DIM, IN_DIM, 1);

    lstm_layer_kernel<<<16, 256>>>(Gf, Gb, f_Whh0, b_Whh0,
                                   h0f, h0b, H_DIM, 0,
                                   cell + 0,   cell + 256,
                                   hid  + 0,   hid  + 256);

    gemm_nt_bias<<<gemm_grid, 256>>>(h0f, f_Wih1, f_bih1, f_bhh1, Gf, T_SEQ, G_DIM, H_DIM, 0);
    gemm_nt_bias<<<gemm_grid, 256>>>(h0b, b_Wih1, b_bih1, b_bhh1, Gb, T_SEQ, G_DIM, H_DIM, 0);

    lstm_layer_kernel<<<16, 256>>>(Gf, Gb, f_Whh1, b_Whh1,
                                   outs, outs + 256, 2 * H_DIM, 1,
                                   cell + 512, cell + 768,
                                   hid  + 512, hid  + 768);
}